// round 1
// baseline (speedup 1.0000x reference)
#include <cuda_runtime.h>
#include <cuda_bf16.h>
#include <stdint.h>

namespace ode {

constexpr int NSTEPS = 32;

__device__ __forceinline__ uint32_t pack_bf2(float lo, float hi) {
    __nv_bfloat162 h = __floats2bfloat162_rn(lo, hi);
    return *reinterpret_cast<uint32_t*>(&h);
}

__device__ __forceinline__ uint32_t pack_bf2h(__nv_bfloat16 lo, __nv_bfloat16 hi) {
    __nv_bfloat162 h = __halves2bfloat162(lo, hi);
    return *reinterpret_cast<uint32_t*>(&h);
}

__device__ __forceinline__ float tanh_fast(float x) {
    float r;
    asm("tanh.approx.f32 %0, %1;" : "=f"(r) : "f"(x));
    return r;
}

__device__ __forceinline__ void mma_bf16(float& c0, float& c1, float& c2, float& c3,
                                         uint32_t a0, uint32_t a1, uint32_t a2, uint32_t a3,
                                         uint32_t b0, uint32_t b1) {
    asm volatile(
        "mma.sync.aligned.m16n8k16.row.col.f32.bf16.bf16.f32 "
        "{%0,%1,%2,%3}, {%4,%5,%6,%7}, {%8,%9}, {%0,%1,%2,%3};"
        : "+f"(c0), "+f"(c1), "+f"(c2), "+f"(c3)
        : "r"(a0), "r"(a1), "r"(a2), "r"(a3), "r"(b0), "r"(b1));
}

// One CTA = 128 threads = 4 warps; each warp owns 16 batch rows (M=16 fragment),
// full N=64 via 8 n-tiles of m16n8k16. State y lives in accumulator-layout
// registers; D-fragments of one eval ARE the A-fragments of the next.
__global__ void __launch_bounds__(128, 3)
ode_rk4(const float* __restrict__ x,
        const float* __restrict__ W_in,
        const float* __restrict__ b_in,
        const float* __restrict__ Wf,
        const float* __restrict__ bfv,
        const float* __restrict__ W_out,
        const float* __restrict__ b_out,
        float* __restrict__ out) {
    __shared__ float sX[64][17];        // padded to kill bank conflicts
    __shared__ float sWin[16 * 64];
    __shared__ float sWout[64 * 16];
    __shared__ float sbin[64];
    __shared__ float sbf[64];
    __shared__ float sbout[16];
    // Pre-packed B fragments: [kt(4)][nt(8)][lane(32)] -> {Whi_b0, Whi_b1, Wlo_b0, Wlo_b1}
    __shared__ uint4 sB[4 * 8 * 32];
    __shared__ float sY[64][65];        // 65: (65 mod 32)=1 -> conflict-free readout

    const int tid  = threadIdx.x;
    const int lane = tid & 31;
    const int warp = tid >> 5;
    const int g    = lane >> 2;   // 0..7  (row group within m16 tile)
    const int lam  = lane & 3;    // 0..3  (column pair selector)
    const long rowbase = (long)blockIdx.x * 64;

    // ---- stage x tile (64 rows x 16 f32), coalesced float4 ----
    {
        const float4* xg = reinterpret_cast<const float4*>(x + rowbase * 16);
        #pragma unroll
        for (int i = 0; i < 2; ++i) {
            int idx = tid + i * 128;            // 0..255 float4s
            float4 v = xg[idx];
            int r = idx >> 2, c = (idx & 3) << 2;
            sX[r][c] = v.x; sX[r][c + 1] = v.y; sX[r][c + 2] = v.z; sX[r][c + 3] = v.w;
        }
    }
    // ---- stage small weights/biases ----
    for (int i = tid; i < 16 * 64; i += 128) sWin[i]  = W_in[i];
    for (int i = tid; i < 64 * 16; i += 128) sWout[i] = W_out[i];
    if (tid < 64) { sbin[tid] = b_in[tid]; sbf[tid] = bfv[tid]; }
    if (tid < 16) sbout[tid] = b_out[tid];

    // ---- build hi/lo bf16 B-fragments for Wf (split kills systematic W rounding) ----
    // m16n8k16 B frag (col-major): b0 halves at k rows (2*lam, 2*lam+1), col g;
    //                              b1 halves at k rows (2*lam+8, 2*lam+9), col g.
    // Warp w fills nt = w and w+4 for all kt, using its own lane's slots.
    #pragma unroll
    for (int kt = 0; kt < 4; ++kt) {
        #pragma unroll
        for (int q = 0; q < 2; ++q) {
            const int nt  = warp + q * 4;
            const int kr  = kt * 16 + lam * 2;
            const int col = nt * 8 + g;
            float w00 = Wf[(kr + 0) * 64 + col];
            float w01 = Wf[(kr + 1) * 64 + col];
            float w10 = Wf[(kr + 8) * 64 + col];
            float w11 = Wf[(kr + 9) * 64 + col];
            __nv_bfloat16 h00 = __float2bfloat16_rn(w00);
            __nv_bfloat16 h01 = __float2bfloat16_rn(w01);
            __nv_bfloat16 h10 = __float2bfloat16_rn(w10);
            __nv_bfloat16 h11 = __float2bfloat16_rn(w11);
            uint4 v;
            v.x = pack_bf2h(h00, h01);
            v.y = pack_bf2h(h10, h11);
            v.z = pack_bf2(w00 - __bfloat162float(h00), w01 - __bfloat162float(h01));
            v.w = pack_bf2(w10 - __bfloat162float(h10), w11 - __bfloat162float(h11));
            sB[(kt * 8 + nt) * 32 + lane] = v;
        }
    }
    __syncthreads();

    // ---- y0 = x @ W_in + b_in, computed directly into fragment layout ----
    // y[nt][c]: c0,c1 -> row r0, cols (nt*8+2*lam, +1); c2,c3 -> row r0+8, same cols.
    const int r0 = warp * 16 + g;
    float y[8][4];
    #pragma unroll
    for (int nt = 0; nt < 8; ++nt) {
        const int c0i = nt * 8 + lam * 2;
        y[nt][0] = sbin[c0i];  y[nt][1] = sbin[c0i + 1];
        y[nt][2] = sbin[c0i];  y[nt][3] = sbin[c0i + 1];
    }
    #pragma unroll 4
    for (int i = 0; i < 16; ++i) {
        float xa = sX[r0][i];
        float xb = sX[r0 + 8][i];
        #pragma unroll
        for (int nt = 0; nt < 8; ++nt) {
            float w0 = sWin[i * 64 + nt * 8 + lam * 2];
            float w1 = sWin[i * 64 + nt * 8 + lam * 2 + 1];
            y[nt][0] = fmaf(xa, w0, y[nt][0]);
            y[nt][1] = fmaf(xa, w1, y[nt][1]);
            y[nt][2] = fmaf(xb, w0, y[nt][2]);
            y[nt][3] = fmaf(xb, w1, y[nt][3]);
        }
    }

    // ---- RK4 over 32 steps; f(y) = tanh(y@Wf + bf) via two bf16 MMAs (hi+lo) ----
    const float DT = 1.0f / 32.0f;
    const float csum[4] = {DT / 6.0f, DT / 3.0f, DT / 3.0f, DT / 6.0f};
    const float cmid[4] = {0.0f, DT * 0.5f, DT * 0.5f, DT};

    float acc[8][4];   // holds k_{e-1} (tanh outputs) in accumulator layout
    #pragma unroll
    for (int nt = 0; nt < 8; ++nt) {
        acc[nt][0] = 0.f; acc[nt][1] = 0.f; acc[nt][2] = 0.f; acc[nt][3] = 0.f;
    }

    for (int step = 0; step < NSTEPS; ++step) {
        float ysum[8][4];
        #pragma unroll
        for (int nt = 0; nt < 8; ++nt) {
            ysum[nt][0] = y[nt][0]; ysum[nt][1] = y[nt][1];
            ysum[nt][2] = y[nt][2]; ysum[nt][3] = y[nt][3];
        }
        #pragma unroll
        for (int e = 0; e < 4; ++e) {
            // A fragments for this eval: a[kt] covers k cols [16kt,16kt+16).
            // D->A identity: A[kt] regs = cvt(D[2kt].c0..c3, D[2kt+1].c0..c3).
            uint32_t a[4][4];
            #pragma unroll
            for (int kt = 0; kt < 4; ++kt) {
                const int nA = 2 * kt, nB = 2 * kt + 1;
                if (e == 0) {
                    a[kt][0] = pack_bf2(y[nA][0], y[nA][1]);
                    a[kt][1] = pack_bf2(y[nA][2], y[nA][3]);
                    a[kt][2] = pack_bf2(y[nB][0], y[nB][1]);
                    a[kt][3] = pack_bf2(y[nB][2], y[nB][3]);
                } else {
                    const float cm = cmid[e];
                    a[kt][0] = pack_bf2(fmaf(cm, acc[nA][0], y[nA][0]),
                                        fmaf(cm, acc[nA][1], y[nA][1]));
                    a[kt][1] = pack_bf2(fmaf(cm, acc[nA][2], y[nA][2]),
                                        fmaf(cm, acc[nA][3], y[nA][3]));
                    a[kt][2] = pack_bf2(fmaf(cm, acc[nB][0], y[nB][0]),
                                        fmaf(cm, acc[nB][1], y[nB][1]));
                    a[kt][3] = pack_bf2(fmaf(cm, acc[nB][2], y[nB][2]),
                                        fmaf(cm, acc[nB][3], y[nB][3]));
                }
            }
            const float cs = csum[e];
            #pragma unroll
            for (int nt = 0; nt < 8; ++nt) {
                const int c0i = nt * 8 + lam * 2;
                float c0 = sbf[c0i], c1 = sbf[c0i + 1];
                float c2 = c0, c3 = c1;
                #pragma unroll
                for (int kt = 0; kt < 4; ++kt) {
                    uint4 b = sB[(kt * 8 + nt) * 32 + lane];   // one LDS.128: hi+lo frags
                    mma_bf16(c0, c1, c2, c3, a[kt][0], a[kt][1], a[kt][2], a[kt][3], b.x, b.y);
                    mma_bf16(c0, c1, c2, c3, a[kt][0], a[kt][1], a[kt][2], a[kt][3], b.z, b.w);
                }
                c0 = tanh_fast(c0); c1 = tanh_fast(c1);
                c2 = tanh_fast(c2); c3 = tanh_fast(c3);
                acc[nt][0] = c0; acc[nt][1] = c1; acc[nt][2] = c2; acc[nt][3] = c3;
                ysum[nt][0] = fmaf(cs, c0, ysum[nt][0]);
                ysum[nt][1] = fmaf(cs, c1, ysum[nt][1]);
                ysum[nt][2] = fmaf(cs, c2, ysum[nt][2]);
                ysum[nt][3] = fmaf(cs, c3, ysum[nt][3]);
            }
        }
        #pragma unroll
        for (int nt = 0; nt < 8; ++nt) {
            y[nt][0] = ysum[nt][0]; y[nt][1] = ysum[nt][1];
            y[nt][2] = ysum[nt][2]; y[nt][3] = ysum[nt][3];
        }
    }

    // ---- readout: stage y1 to SMEM, then out = y1 @ W_out + b_out (fp32) ----
    #pragma unroll
    for (int nt = 0; nt < 8; ++nt) {
        const int c0i = nt * 8 + lam * 2;
        sY[r0][c0i]     = y[nt][0];  sY[r0][c0i + 1]     = y[nt][1];
        sY[r0 + 8][c0i] = y[nt][2];  sY[r0 + 8][c0i + 1] = y[nt][3];
    }
    __syncthreads();
    {
        const int orow = tid >> 1;          // 0..63
        const int ocol = (tid & 1) * 8;     // 0 or 8
        float o[8];
        #pragma unroll
        for (int j = 0; j < 8; ++j) o[j] = sbout[ocol + j];
        #pragma unroll 4
        for (int k = 0; k < 64; ++k) {
            float yv = sY[orow][k];
            #pragma unroll
            for (int j = 0; j < 8; ++j)
                o[j] = fmaf(yv, sWout[k * 16 + ocol + j], o[j]);
        }
        float4* og = reinterpret_cast<float4*>(out + (rowbase + orow) * 16 + ocol);
        og[0] = make_float4(o[0], o[1], o[2], o[3]);
        og[1] = make_float4(o[4], o[5], o[6], o[7]);
    }
}

}  // namespace ode

extern "C" void kernel_launch(void* const* d_in, const int* in_sizes, int n_in,
                              void* d_out, int out_size) {
    const float* x     = (const float*)d_in[0];
    const float* W_in  = (const float*)d_in[1];
    const float* b_in  = (const float*)d_in[2];
    const float* Wf    = (const float*)d_in[3];
    const float* bfv   = (const float*)d_in[4];
    const float* W_out = (const float*)d_in[5];
    const float* b_out = (const float*)d_in[6];
    float* out = (float*)d_out;

    const int batch = in_sizes[0] / 16;     // x is [B, 16]
    const int grid  = batch / 64;           // 64 rows per CTA
    ode::ode_rk4<<<grid, 128>>>(x, W_in, b_in, Wf, bfv, W_out, b_out, out);
}

// round 2
// speedup vs baseline: 1.9253x; 1.9253x over previous
#include <cuda_runtime.h>
#include <cuda_bf16.h>
#include <stdint.h>

namespace ode {

constexpr int NSTEPS = 32;

__device__ __forceinline__ uint32_t pack_bf2(float lo, float hi) {
    __nv_bfloat162 h = __floats2bfloat162_rn(lo, hi);
    return *reinterpret_cast<uint32_t*>(&h);
}

__device__ __forceinline__ uint32_t pack_bf2h(__nv_bfloat16 lo, __nv_bfloat16 hi) {
    __nv_bfloat162 h = __halves2bfloat162(lo, hi);
    return *reinterpret_cast<uint32_t*>(&h);
}

__device__ __forceinline__ float tanh_fast(float x) {
    float r;
    asm("tanh.approx.f32 %0, %1;" : "=f"(r) : "f"(x));
    return r;
}

__device__ __forceinline__ void mma_bf16(float& c0, float& c1, float& c2, float& c3,
                                         uint32_t a0, uint32_t a1, uint32_t a2, uint32_t a3,
                                         uint32_t b0, uint32_t b1) {
    asm volatile(
        "mma.sync.aligned.m16n8k16.row.col.f32.bf16.bf16.f32 "
        "{%0,%1,%2,%3}, {%4,%5,%6,%7}, {%8,%9}, {%0,%1,%2,%3};"
        : "+f"(c0), "+f"(c1), "+f"(c2), "+f"(c3)
        : "r"(a0), "r"(a1), "r"(a2), "r"(a3), "r"(b0), "r"(b1));
}

// One CTA = 128 threads = 4 warps; each warp owns 16 batch rows (M=16 fragment),
// full N=64 via 8 n-tiles of m16n8k16. State y lives in accumulator-layout
// registers; D-fragments of one eval ARE the A-fragments of the next.
// R1 change: Whi/Wlo B-fragments live in REGISTERS (128 u32/thread) instead of
// SMEM — removes the L1-crossbar bottleneck (84% busy in R0 profile).
__global__ void __launch_bounds__(128, 2)
ode_rk4(const float* __restrict__ x,
        const float* __restrict__ W_in,
        const float* __restrict__ b_in,
        const float* __restrict__ Wf,
        const float* __restrict__ bfv,
        const float* __restrict__ W_out,
        const float* __restrict__ b_out,
        float* __restrict__ out) {
    __shared__ float sX[64][17];
    __shared__ float sWin[16 * 64];
    __shared__ float sWout[64 * 16];
    __shared__ float sbin[64];
    __shared__ float sbf[64];
    __shared__ float sbout[16];
    __shared__ float sY[64][65];

    const int tid  = threadIdx.x;
    const int lane = tid & 31;
    const int warp = tid >> 5;
    const int g    = lane >> 2;   // 0..7  (row group within m16 tile)
    const int lam  = lane & 3;    // 0..3  (column pair selector)
    const long rowbase = (long)blockIdx.x * 64;

    // ---- stage x tile (64 rows x 16 f32), coalesced float4 ----
    {
        const float4* xg = reinterpret_cast<const float4*>(x + rowbase * 16);
        #pragma unroll
        for (int i = 0; i < 2; ++i) {
            int idx = tid + i * 128;
            float4 v = xg[idx];
            int r = idx >> 2, c = (idx & 3) << 2;
            sX[r][c] = v.x; sX[r][c + 1] = v.y; sX[r][c + 2] = v.z; sX[r][c + 3] = v.w;
        }
    }
    for (int i = tid; i < 16 * 64; i += 128) sWin[i]  = W_in[i];
    for (int i = tid; i < 64 * 16; i += 128) sWout[i] = W_out[i];
    if (tid < 64) { sbin[tid] = b_in[tid]; sbf[tid] = bfv[tid]; }
    if (tid < 16) sbout[tid] = b_out[tid];

    // ---- build hi/lo bf16 B-fragments for Wf directly into registers ----
    // m16n8k16 B frag (col-major): b0 halves at k rows (2*lam, 2*lam+1), col g;
    //                              b1 halves at k rows (2*lam+8, 2*lam+9), col g.
    uint32_t Bh[4][8][2];
    uint32_t Bl[4][8][2];
    #pragma unroll
    for (int kt = 0; kt < 4; ++kt) {
        #pragma unroll
        for (int nt = 0; nt < 8; ++nt) {
            const float* wp = Wf + (kt * 16 + lam * 2) * 64 + nt * 8 + g;
            float w00 = __ldg(wp);
            float w01 = __ldg(wp + 64);
            float w10 = __ldg(wp + 8 * 64);
            float w11 = __ldg(wp + 9 * 64);
            __nv_bfloat16 h00 = __float2bfloat16_rn(w00);
            __nv_bfloat16 h01 = __float2bfloat16_rn(w01);
            __nv_bfloat16 h10 = __float2bfloat16_rn(w10);
            __nv_bfloat16 h11 = __float2bfloat16_rn(w11);
            Bh[kt][nt][0] = pack_bf2h(h00, h01);
            Bh[kt][nt][1] = pack_bf2h(h10, h11);
            Bl[kt][nt][0] = pack_bf2(w00 - __bfloat162float(h00), w01 - __bfloat162float(h01));
            Bl[kt][nt][1] = pack_bf2(w10 - __bfloat162float(h10), w11 - __bfloat162float(h11));
        }
    }
    __syncthreads();

    // ---- y0 = x @ W_in + b_in, computed directly into fragment layout ----
    const int r0 = warp * 16 + g;
    float y[8][4];
    #pragma unroll
    for (int nt = 0; nt < 8; ++nt) {
        const int c0i = nt * 8 + lam * 2;
        y[nt][0] = sbin[c0i];  y[nt][1] = sbin[c0i + 1];
        y[nt][2] = sbin[c0i];  y[nt][3] = sbin[c0i + 1];
    }
    #pragma unroll 4
    for (int i = 0; i < 16; ++i) {
        float xa = sX[r0][i];
        float xb = sX[r0 + 8][i];
        #pragma unroll
        for (int nt = 0; nt < 8; ++nt) {
            float w0 = sWin[i * 64 + nt * 8 + lam * 2];
            float w1 = sWin[i * 64 + nt * 8 + lam * 2 + 1];
            y[nt][0] = fmaf(xa, w0, y[nt][0]);
            y[nt][1] = fmaf(xa, w1, y[nt][1]);
            y[nt][2] = fmaf(xb, w0, y[nt][2]);
            y[nt][3] = fmaf(xb, w1, y[nt][3]);
        }
    }

    // ---- RK4 over 32 steps; f(y) = tanh(y@Wf + bf) via two bf16 MMAs (hi+lo) ----
    const float DT = 1.0f / 32.0f;
    const float csum[4]  = {DT / 6.0f, DT / 3.0f, DT / 3.0f, DT / 6.0f};
    const float cmidn[4] = {DT * 0.5f, DT * 0.5f, DT, 0.0f};  // cmid for eval e+1

    // A fragments for the current eval; an = fragments for the next eval,
    // built incrementally as tanh outputs are produced (replaces acc[] storage).
    uint32_t a[4][4], an[4][4];
    #pragma unroll
    for (int kt = 0; kt < 4; ++kt) {
        a[kt][0] = pack_bf2(y[2 * kt][0],     y[2 * kt][1]);
        a[kt][1] = pack_bf2(y[2 * kt][2],     y[2 * kt][3]);
        a[kt][2] = pack_bf2(y[2 * kt + 1][0], y[2 * kt + 1][1]);
        a[kt][3] = pack_bf2(y[2 * kt + 1][2], y[2 * kt + 1][3]);
    }

    float ysum[8][4];
    for (int step = 0; step < NSTEPS; ++step) {
        #pragma unroll
        for (int nt = 0; nt < 8; ++nt) {
            ysum[nt][0] = y[nt][0]; ysum[nt][1] = y[nt][1];
            ysum[nt][2] = y[nt][2]; ysum[nt][3] = y[nt][3];
        }
        #pragma unroll
        for (int e = 0; e < 4; ++e) {
            const float cs  = csum[e];
            const float cmn = cmidn[e];
            #pragma unroll
            for (int nt = 0; nt < 8; ++nt) {
                const float2 bb = *reinterpret_cast<const float2*>(&sbf[nt * 8 + lam * 2]);
                float c0 = bb.x, c1 = bb.y, c2 = bb.x, c3 = bb.y;
                #pragma unroll
                for (int kt = 0; kt < 4; ++kt) {
                    mma_bf16(c0, c1, c2, c3, a[kt][0], a[kt][1], a[kt][2], a[kt][3],
                             Bh[kt][nt][0], Bh[kt][nt][1]);
                    mma_bf16(c0, c1, c2, c3, a[kt][0], a[kt][1], a[kt][2], a[kt][3],
                             Bl[kt][nt][0], Bl[kt][nt][1]);
                }
                c0 = tanh_fast(c0); c1 = tanh_fast(c1);
                c2 = tanh_fast(c2); c3 = tanh_fast(c3);
                ysum[nt][0] = fmaf(cs, c0, ysum[nt][0]);
                ysum[nt][1] = fmaf(cs, c1, ysum[nt][1]);
                ysum[nt][2] = fmaf(cs, c2, ysum[nt][2]);
                ysum[nt][3] = fmaf(cs, c3, ysum[nt][3]);
                const int kt2 = nt >> 1;
                const int sl  = (nt & 1) * 2;   // slots 0,1 for even nt; 2,3 for odd
                if (e < 3) {
                    an[kt2][sl]     = pack_bf2(fmaf(cmn, c0, y[nt][0]),
                                               fmaf(cmn, c1, y[nt][1]));
                    an[kt2][sl + 1] = pack_bf2(fmaf(cmn, c2, y[nt][2]),
                                               fmaf(cmn, c3, y[nt][3]));
                } else {
                    // finalize y for this step; next eval (e0 of next step) uses y itself
                    y[nt][0] = ysum[nt][0]; y[nt][1] = ysum[nt][1];
                    y[nt][2] = ysum[nt][2]; y[nt][3] = ysum[nt][3];
                    an[kt2][sl]     = pack_bf2(y[nt][0], y[nt][1]);
                    an[kt2][sl + 1] = pack_bf2(y[nt][2], y[nt][3]);
                }
            }
            #pragma unroll
            for (int kt = 0; kt < 4; ++kt) {
                a[kt][0] = an[kt][0]; a[kt][1] = an[kt][1];
                a[kt][2] = an[kt][2]; a[kt][3] = an[kt][3];
            }
        }
    }

    // ---- readout: stage y1 to SMEM, then out = y1 @ W_out + b_out (fp32) ----
    #pragma unroll
    for (int nt = 0; nt < 8; ++nt) {
        const int c0i = nt * 8 + lam * 2;
        sY[r0][c0i]     = y[nt][0];  sY[r0][c0i + 1]     = y[nt][1];
        sY[r0 + 8][c0i] = y[nt][2];  sY[r0 + 8][c0i + 1] = y[nt][3];
    }
    __syncthreads();
    {
        const int orow = tid >> 1;
        const int ocol = (tid & 1) * 8;
        float o[8];
        #pragma unroll
        for (int j = 0; j < 8; ++j) o[j] = sbout[ocol + j];
        #pragma unroll 4
        for (int k = 0; k < 64; ++k) {
            float yv = sY[orow][k];
            #pragma unroll
            for (int j = 0; j < 8; ++j)
                o[j] = fmaf(yv, sWout[k * 16 + ocol + j], o[j]);
        }
        float4* og = reinterpret_cast<float4*>(out + (rowbase + orow) * 16 + ocol);
        og[0] = make_float4(o[0], o[1], o[2], o[3]);
        og[1] = make_float4(o[4], o[5], o[6], o[7]);
    }
}

}  // namespace ode

extern "C" void kernel_launch(void* const* d_in, const int* in_sizes, int n_in,
                              void* d_out, int out_size) {
    const float* x     = (const float*)d_in[0];
    const float* W_in  = (const float*)d_in[1];
    const float* b_in  = (const float*)d_in[2];
    const float* Wf    = (const float*)d_in[3];
    const float* bfv   = (const float*)d_in[4];
    const float* W_out = (const float*)d_in[5];
    const float* b_out = (const float*)d_in[6];
    float* out = (float*)d_out;

    const int batch = in_sizes[0] / 16;
    const int grid  = batch / 64;
    ode::ode_rk4<<<grid, 128>>>(x, W_in, b_in, Wf, bfv, W_out, b_out, out);
}

// round 4
// speedup vs baseline: 2.9430x; 1.5286x over previous
#include <cuda_runtime.h>
#include <cuda_bf16.h>
#include <stdint.h>

namespace ode {

constexpr int NSTEPS = 32;

__device__ __forceinline__ uint32_t pack_bf2(float lo, float hi) {
    __nv_bfloat162 h = __floats2bfloat162_rn(lo, hi);
    return *reinterpret_cast<uint32_t*>(&h);
}
__device__ __forceinline__ uint32_t pack_bf2h(__nv_bfloat16 lo, __nv_bfloat16 hi) {
    __nv_bfloat162 h = __halves2bfloat162(lo, hi);
    return *reinterpret_cast<uint32_t*>(&h);
}
__device__ __forceinline__ float tanh_fast(float x) {
    float r;
    asm("tanh.approx.f32 %0, %1;" : "=f"(r) : "f"(x));
    return r;
}
// exact bf16 -> f32 via bit ops
__device__ __forceinline__ float bf_lo(uint32_t p) { return __uint_as_float(p << 16); }
__device__ __forceinline__ float bf_hi(uint32_t p) { return __uint_as_float(p & 0xffff0000u); }

__device__ __forceinline__ void mma_bf16(float& c0, float& c1, float& c2, float& c3,
                                         uint32_t a0, uint32_t a1, uint32_t a2, uint32_t a3,
                                         uint32_t b0, uint32_t b1) {
    asm volatile(
        "mma.sync.aligned.m16n8k16.row.col.f32.bf16.bf16.f32 "
        "{%0,%1,%2,%3}, {%4,%5,%6,%7}, {%8,%9}, {%0,%1,%2,%3};"
        : "+f"(c0), "+f"(c1), "+f"(c2), "+f"(c3)
        : "r"(a0), "r"(a1), "r"(a2), "r"(a3), "r"(b0), "r"(b1));
}

// RK4 in incremental (delta-z) form with drift correction:
//   z = y@Wf + bf carried in fp32; per step:
//     k1 = tanh(z)                         (no matmul)
//     z_e = z + (c_e k)@Whi                (3 hi-only increment matmuls)
//     z  += u@Whi + u@Wlo, u = dt/6*sum    (2 matmuls; lo kills systematic drift)
//   => 160 HMMA/step vs 256 in the direct hi/lo form. tanh in f32 (MUFU).
__global__ void __launch_bounds__(128, 2)
ode_rk4(const float* __restrict__ x,
        const float* __restrict__ W_in,
        const float* __restrict__ b_in,
        const float* __restrict__ Wf,
        const float* __restrict__ bfv,
        const float* __restrict__ W_out,
        const float* __restrict__ b_out,
        float* __restrict__ out) {
    __shared__ float sX[64][17];
    __shared__ float sWin[16 * 64];
    __shared__ float sWout[64 * 16];
    __shared__ float sbin[64];
    __shared__ float sbf[64];
    __shared__ float sbout[16];
    __shared__ float sY[64][65];
    __shared__ uint2 sBl[4][8][32];   // Wlo B-fragments (used once/step -> SMEM ok)

    const int tid  = threadIdx.x;
    const int lane = tid & 31;
    const int warp = tid >> 5;
    const int g    = lane >> 2;
    const int lam  = lane & 3;
    const long rowbase = (long)blockIdx.x * 64;

    // ---- stage x tile ----
    {
        const float4* xg = reinterpret_cast<const float4*>(x + rowbase * 16);
        #pragma unroll
        for (int i = 0; i < 2; ++i) {
            int idx = tid + i * 128;
            float4 v = xg[idx];
            int r = idx >> 2, c = (idx & 3) << 2;
            sX[r][c] = v.x; sX[r][c + 1] = v.y; sX[r][c + 2] = v.z; sX[r][c + 3] = v.w;
        }
    }
    for (int i = tid; i < 16 * 64; i += 128) sWin[i]  = W_in[i];
    for (int i = tid; i < 64 * 16; i += 128) sWout[i] = W_out[i];
    if (tid < 64) { sbin[tid] = b_in[tid]; sbf[tid] = bfv[tid]; }
    if (tid < 16) sbout[tid] = b_out[tid];

    // ---- Whi fragments in registers; Wlo fragments to SMEM ----
    uint32_t Bh[4][8][2];
    #pragma unroll
    for (int kt = 0; kt < 4; ++kt) {
        #pragma unroll
        for (int nt = 0; nt < 8; ++nt) {
            const float* wp = Wf + (kt * 16 + lam * 2) * 64 + nt * 8 + g;
            float w00 = __ldg(wp);
            float w01 = __ldg(wp + 64);
            float w10 = __ldg(wp + 8 * 64);
            float w11 = __ldg(wp + 9 * 64);
            __nv_bfloat16 h00 = __float2bfloat16_rn(w00);
            __nv_bfloat16 h01 = __float2bfloat16_rn(w01);
            __nv_bfloat16 h10 = __float2bfloat16_rn(w10);
            __nv_bfloat16 h11 = __float2bfloat16_rn(w11);
            Bh[kt][nt][0] = pack_bf2h(h00, h01);
            Bh[kt][nt][1] = pack_bf2h(h10, h11);
            uint2 lo;
            lo.x = pack_bf2(w00 - __bfloat162float(h00), w01 - __bfloat162float(h01));
            lo.y = pack_bf2(w10 - __bfloat162float(h10), w11 - __bfloat162float(h11));
            sBl[kt][nt][lane] = lo;
        }
    }
    __syncthreads();

    // ---- y0 = x @ W_in + b_in (fp32, fragment layout) ----
    const int r0 = warp * 16 + g;
    float y[8][4];
    #pragma unroll
    for (int nt = 0; nt < 8; ++nt) {
        const int c0i = nt * 8 + lam * 2;
        y[nt][0] = sbin[c0i];  y[nt][1] = sbin[c0i + 1];
        y[nt][2] = sbin[c0i];  y[nt][3] = sbin[c0i + 1];
    }
    #pragma unroll 4
    for (int i = 0; i < 16; ++i) {
        float xa = sX[r0][i];
        float xb = sX[r0 + 8][i];
        #pragma unroll
        for (int nt = 0; nt < 8; ++nt) {
            float w0 = sWin[i * 64 + nt * 8 + lam * 2];
            float w1 = sWin[i * 64 + nt * 8 + lam * 2 + 1];
            y[nt][0] = fmaf(xa, w0, y[nt][0]);
            y[nt][1] = fmaf(xa, w1, y[nt][1]);
            y[nt][2] = fmaf(xb, w0, y[nt][2]);
            y[nt][3] = fmaf(xb, w1, y[nt][3]);
        }
    }

    // ---- base z0 = y0 @ Wf + bf, high precision: y0h@(Whi+Wlo) + y0l@Whi ----
    float z[8][4];
    {
        uint32_t ah[4][4], al[4][4];
        #pragma unroll
        for (int kt = 0; kt < 4; ++kt) {
            const int nA = 2 * kt, nB = 2 * kt + 1;
            ah[kt][0] = pack_bf2(y[nA][0], y[nA][1]);
            ah[kt][1] = pack_bf2(y[nA][2], y[nA][3]);
            ah[kt][2] = pack_bf2(y[nB][0], y[nB][1]);
            ah[kt][3] = pack_bf2(y[nB][2], y[nB][3]);
            al[kt][0] = pack_bf2(y[nA][0] - bf_lo(ah[kt][0]), y[nA][1] - bf_hi(ah[kt][0]));
            al[kt][1] = pack_bf2(y[nA][2] - bf_lo(ah[kt][1]), y[nA][3] - bf_hi(ah[kt][1]));
            al[kt][2] = pack_bf2(y[nB][0] - bf_lo(ah[kt][2]), y[nB][1] - bf_hi(ah[kt][2]));
            al[kt][3] = pack_bf2(y[nB][2] - bf_lo(ah[kt][3]), y[nB][3] - bf_hi(ah[kt][3]));
        }
        #pragma unroll
        for (int nt = 0; nt < 8; ++nt) {
            const float2 bb = *reinterpret_cast<const float2*>(&sbf[nt * 8 + lam * 2]);
            z[nt][0] = bb.x; z[nt][1] = bb.y; z[nt][2] = bb.x; z[nt][3] = bb.y;
            #pragma unroll
            for (int kt = 0; kt < 4; ++kt) {
                uint2 bl = sBl[kt][nt][lane];
                mma_bf16(z[nt][0], z[nt][1], z[nt][2], z[nt][3],
                         ah[kt][0], ah[kt][1], ah[kt][2], ah[kt][3],
                         Bh[kt][nt][0], Bh[kt][nt][1]);
                mma_bf16(z[nt][0], z[nt][1], z[nt][2], z[nt][3],
                         ah[kt][0], ah[kt][1], ah[kt][2], ah[kt][3],
                         bl.x, bl.y);
                mma_bf16(z[nt][0], z[nt][1], z[nt][2], z[nt][3],
                         al[kt][0], al[kt][1], al[kt][2], al[kt][3],
                         Bh[kt][nt][0], Bh[kt][nt][1]);
            }
        }
    }

    // ---- RK4 main loop, incremental form ----
    const float DT   = 1.0f / 32.0f;
    const float DT6  = DT / 6.0f;
    const float CMID[3] = {DT * 0.5f, DT * 0.5f, DT};   // A-scale feeding evals e2,e3,e4
    const float SW[3]   = {2.0f, 2.0f, 1.0f};           // s-weight of k2,k3,k4

    float s[8][4];
    uint32_t a[4][4], an[4][4];

    for (int step = 0; step < NSTEPS; ++step) {
        // e1: k1 = tanh(z); s = k1; a = pack(dt/2 * k1)
        #pragma unroll
        for (int nt = 0; nt < 8; ++nt) {
            float k0 = tanh_fast(z[nt][0]);
            float k1 = tanh_fast(z[nt][1]);
            float k2 = tanh_fast(z[nt][2]);
            float k3 = tanh_fast(z[nt][3]);
            s[nt][0] = k0; s[nt][1] = k1; s[nt][2] = k2; s[nt][3] = k3;
            const int kt2 = nt >> 1, sl = (nt & 1) * 2;
            a[kt2][sl]     = pack_bf2(CMID[0] * k0, CMID[0] * k1);
            a[kt2][sl + 1] = pack_bf2(CMID[0] * k2, CMID[0] * k3);
        }
        // e2..e4: z_e = z + a@Whi ; k = tanh(z_e); s += w*k ; a_next = pack(c*k)
        #pragma unroll
        for (int e = 0; e < 3; ++e) {
            const float sw = SW[e];
            const float cm = (e < 2) ? CMID[e + 1] : 0.0f;  // e4 produces no next A
            #pragma unroll
            for (int nt = 0; nt < 8; ++nt) {
                float c0 = z[nt][0], c1 = z[nt][1], c2 = z[nt][2], c3 = z[nt][3];
                #pragma unroll
                for (int kt = 0; kt < 4; ++kt)
                    mma_bf16(c0, c1, c2, c3,
                             a[kt][0], a[kt][1], a[kt][2], a[kt][3],
                             Bh[kt][nt][0], Bh[kt][nt][1]);
                c0 = tanh_fast(c0); c1 = tanh_fast(c1);
                c2 = tanh_fast(c2); c3 = tanh_fast(c3);
                s[nt][0] = fmaf(sw, c0, s[nt][0]);
                s[nt][1] = fmaf(sw, c1, s[nt][1]);
                s[nt][2] = fmaf(sw, c2, s[nt][2]);
                s[nt][3] = fmaf(sw, c3, s[nt][3]);
                if (e < 2) {
                    const int kt2 = nt >> 1, sl = (nt & 1) * 2;
                    an[kt2][sl]     = pack_bf2(cm * c0, cm * c1);
                    an[kt2][sl + 1] = pack_bf2(cm * c2, cm * c3);
                }
            }
            if (e < 2) {
                #pragma unroll
                for (int kt = 0; kt < 4; ++kt) {
                    a[kt][0] = an[kt][0]; a[kt][1] = an[kt][1];
                    a[kt][2] = an[kt][2]; a[kt][3] = an[kt][3];
                }
            }
        }
        // step: u = dt/6*s; y += u; z += u@Whi + u@Wlo
        #pragma unroll
        for (int nt = 0; nt < 8; ++nt) {
            float u0 = DT6 * s[nt][0], u1 = DT6 * s[nt][1];
            float u2 = DT6 * s[nt][2], u3 = DT6 * s[nt][3];
            y[nt][0] += u0; y[nt][1] += u1; y[nt][2] += u2; y[nt][3] += u3;
            const int kt2 = nt >> 1, sl = (nt & 1) * 2;
            a[kt2][sl]     = pack_bf2(u0, u1);
            a[kt2][sl + 1] = pack_bf2(u2, u3);
        }
        #pragma unroll
        for (int nt = 0; nt < 8; ++nt) {
            #pragma unroll
            for (int kt = 0; kt < 4; ++kt) {
                uint2 bl = sBl[kt][nt][lane];
                mma_bf16(z[nt][0], z[nt][1], z[nt][2], z[nt][3],
                         a[kt][0], a[kt][1], a[kt][2], a[kt][3],
                         Bh[kt][nt][0], Bh[kt][nt][1]);
                mma_bf16(z[nt][0], z[nt][1], z[nt][2], z[nt][3],
                         a[kt][0], a[kt][1], a[kt][2], a[kt][3],
                         bl.x, bl.y);
            }
        }
    }

    // ---- readout: out = y1 @ W_out + b_out (fp32) ----
    #pragma unroll
    for (int nt = 0; nt < 8; ++nt) {
        const int c0i = nt * 8 + lam * 2;
        sY[r0][c0i]     = y[nt][0];  sY[r0][c0i + 1]     = y[nt][1];
        sY[r0 + 8][c0i] = y[nt][2];  sY[r0 + 8][c0i + 1] = y[nt][3];
    }
    __syncthreads();
    {
        const int orow = tid >> 1;
        const int ocol = (tid & 1) * 8;
        float o[8];
        #pragma unroll
        for (int j = 0; j < 8; ++j) o[j] = sbout[ocol + j];
        #pragma unroll 4
        for (int k = 0; k < 64; ++k) {
            float yv = sY[orow][k];
            #pragma unroll
            for (int j = 0; j < 8; ++j)
                o[j] = fmaf(yv, sWout[k * 16 + ocol + j], o[j]);
        }
        float4* og = reinterpret_cast<float4*>(out + (rowbase + orow) * 16 + ocol);
        og[0] = make_float4(o[0], o[1], o[2], o[3]);
        og[1] = make_float4(o[4], o[5], o[6], o[7]);
    }
}

}  // namespace ode

extern "C" void kernel_launch(void* const* d_in, const int* in_sizes, int n_in,
                              void* d_out, int out_size) {
    const float* x     = (const float*)d_in[0];
    const float* W_in  = (const float*)d_in[1];
    const float* b_in  = (const float*)d_in[2];
    const float* Wf    = (const float*)d_in[3];
    const float* bfv   = (const float*)d_in[4];
    const float* W_out = (const float*)d_in[5];
    const float* b_out = (const float*)d_in[6];
    float* out = (float*)d_out;

    const int batch = in_sizes[0] / 16;
    const int grid  = batch / 64;
    ode::ode_rk4<<<grid, 128>>>(x, W_in, b_in, Wf, bfv, W_out, b_out, out);
}

// round 5
// speedup vs baseline: 3.2870x; 1.1169x over previous
#include <cuda_runtime.h>
#include <cuda_fp16.h>
#include <stdint.h>

namespace ode {

constexpr int NSTEPS = 32;

__device__ __forceinline__ uint32_t pack_h2(float lo, float hi) {
    __half2 h = __floats2half2_rn(lo, hi);
    return *reinterpret_cast<uint32_t*>(&h);
}
__device__ __forceinline__ uint32_t pack_h2h(__half lo, __half hi) {
    __half2 h = __halves2half2(lo, hi);
    return *reinterpret_cast<uint32_t*>(&h);
}
__device__ __forceinline__ float h_lo(uint32_t p) {
    __half2 h = *reinterpret_cast<__half2*>(&p);
    return __half2float(__low2half(h));
}
__device__ __forceinline__ float h_hi(uint32_t p) {
    __half2 h = *reinterpret_cast<__half2*>(&p);
    return __half2float(__high2half(h));
}
__device__ __forceinline__ float tanh_fast(float x) {
    float r;
    asm("tanh.approx.f32 %0, %1;" : "=f"(r) : "f"(x));
    return r;
}

__device__ __forceinline__ void mma_f16(float& c0, float& c1, float& c2, float& c3,
                                        uint32_t a0, uint32_t a1, uint32_t a2, uint32_t a3,
                                        uint32_t b0, uint32_t b1) {
    asm volatile(
        "mma.sync.aligned.m16n8k16.row.col.f32.f16.f16.f32 "
        "{%0,%1,%2,%3}, {%4,%5,%6,%7}, {%8,%9}, {%0,%1,%2,%3};"
        : "+f"(c0), "+f"(c1), "+f"(c2), "+f"(c3)
        : "r"(a0), "r"(a1), "r"(a2), "r"(a3), "r"(b0), "r"(b1));
}

// RK4 in incremental (delta-z) form, fp16 weights:
//   z = y@Wf + bf carried in fp32; per step:
//     k1 = tanh(z)                       (no matmul)
//     z_e = z + (c_e k)@Whi              (3 fp16 increment matmuls)
//     z  += u@Whi,  u = dt/6 * sum(k)    (1 matmul)
//   fp16 W-residual is 8x smaller than bf16 -> drift term ~1.6e-4, no per-step
//   lo correction needed. 128 HMMA/step. Wlo used once for the base z0.
__global__ void __launch_bounds__(128, 2)
ode_rk4(const float* __restrict__ x,
        const float* __restrict__ W_in,
        const float* __restrict__ b_in,
        const float* __restrict__ Wf,
        const float* __restrict__ bfv,
        const float* __restrict__ W_out,
        const float* __restrict__ b_out,
        float* __restrict__ out) {
    __shared__ float sX[64][17];
    __shared__ float sWin[16 * 64];
    __shared__ float sWout[64 * 16];
    __shared__ float sbin[64];
    __shared__ float sbf[64];
    __shared__ float sbout[16];
    __shared__ float sY[64][65];
    __shared__ uint2 sBl[4][8][32];   // Wlo fp16 residual fragments (base z0 only)

    const int tid  = threadIdx.x;
    const int lane = tid & 31;
    const int warp = tid >> 5;
    const int g    = lane >> 2;
    const int lam  = lane & 3;
    const long rowbase = (long)blockIdx.x * 64;

    // ---- stage x tile ----
    {
        const float4* xg = reinterpret_cast<const float4*>(x + rowbase * 16);
        #pragma unroll
        for (int i = 0; i < 2; ++i) {
            int idx = tid + i * 128;
            float4 v = xg[idx];
            int r = idx >> 2, c = (idx & 3) << 2;
            sX[r][c] = v.x; sX[r][c + 1] = v.y; sX[r][c + 2] = v.z; sX[r][c + 3] = v.w;
        }
    }
    for (int i = tid; i < 16 * 64; i += 128) sWin[i]  = W_in[i];
    for (int i = tid; i < 64 * 16; i += 128) sWout[i] = W_out[i];
    if (tid < 64) { sbin[tid] = b_in[tid]; sbf[tid] = bfv[tid]; }
    if (tid < 16) sbout[tid] = b_out[tid];

    // ---- Whi (fp16) fragments in registers; Wlo residuals to SMEM ----
    uint32_t Bh[4][8][2];
    #pragma unroll
    for (int kt = 0; kt < 4; ++kt) {
        #pragma unroll
        for (int nt = 0; nt < 8; ++nt) {
            const float* wp = Wf + (kt * 16 + lam * 2) * 64 + nt * 8 + g;
            float w00 = __ldg(wp);
            float w01 = __ldg(wp + 64);
            float w10 = __ldg(wp + 8 * 64);
            float w11 = __ldg(wp + 9 * 64);
            __half h00 = __float2half_rn(w00);
            __half h01 = __float2half_rn(w01);
            __half h10 = __float2half_rn(w10);
            __half h11 = __float2half_rn(w11);
            Bh[kt][nt][0] = pack_h2h(h00, h01);
            Bh[kt][nt][1] = pack_h2h(h10, h11);
            uint2 lo;
            lo.x = pack_h2(w00 - __half2float(h00), w01 - __half2float(h01));
            lo.y = pack_h2(w10 - __half2float(h10), w11 - __half2float(h11));
            sBl[kt][nt][lane] = lo;
        }
    }
    __syncthreads();

    // ---- y0 = x @ W_in + b_in (fp32, fragment layout) ----
    const int r0 = warp * 16 + g;
    float y[8][4];
    #pragma unroll
    for (int nt = 0; nt < 8; ++nt) {
        const int c0i = nt * 8 + lam * 2;
        y[nt][0] = sbin[c0i];  y[nt][1] = sbin[c0i + 1];
        y[nt][2] = sbin[c0i];  y[nt][3] = sbin[c0i + 1];
    }
    #pragma unroll 4
    for (int i = 0; i < 16; ++i) {
        float xa = sX[r0][i];
        float xb = sX[r0 + 8][i];
        #pragma unroll
        for (int nt = 0; nt < 8; ++nt) {
            float w0 = sWin[i * 64 + nt * 8 + lam * 2];
            float w1 = sWin[i * 64 + nt * 8 + lam * 2 + 1];
            y[nt][0] = fmaf(xa, w0, y[nt][0]);
            y[nt][1] = fmaf(xa, w1, y[nt][1]);
            y[nt][2] = fmaf(xb, w0, y[nt][2]);
            y[nt][3] = fmaf(xb, w1, y[nt][3]);
        }
    }

    // ---- base z0 = y0 @ Wf + bf, high precision: y0h@(Whi+Wlo) + y0l@Whi ----
    float z[8][4];
    {
        uint32_t ah[4][4], al[4][4];
        #pragma unroll
        for (int kt = 0; kt < 4; ++kt) {
            const int nA = 2 * kt, nB = 2 * kt + 1;
            ah[kt][0] = pack_h2(y[nA][0], y[nA][1]);
            ah[kt][1] = pack_h2(y[nA][2], y[nA][3]);
            ah[kt][2] = pack_h2(y[nB][0], y[nB][1]);
            ah[kt][3] = pack_h2(y[nB][2], y[nB][3]);
            al[kt][0] = pack_h2(y[nA][0] - h_lo(ah[kt][0]), y[nA][1] - h_hi(ah[kt][0]));
            al[kt][1] = pack_h2(y[nA][2] - h_lo(ah[kt][1]), y[nA][3] - h_hi(ah[kt][1]));
            al[kt][2] = pack_h2(y[nB][0] - h_lo(ah[kt][2]), y[nB][1] - h_hi(ah[kt][2]));
            al[kt][3] = pack_h2(y[nB][2] - h_lo(ah[kt][3]), y[nB][3] - h_hi(ah[kt][3]));
        }
        #pragma unroll
        for (int nt = 0; nt < 8; ++nt) {
            const float2 bb = *reinterpret_cast<const float2*>(&sbf[nt * 8 + lam * 2]);
            z[nt][0] = bb.x; z[nt][1] = bb.y; z[nt][2] = bb.x; z[nt][3] = bb.y;
            #pragma unroll
            for (int kt = 0; kt < 4; ++kt) {
                uint2 bl = sBl[kt][nt][lane];
                mma_f16(z[nt][0], z[nt][1], z[nt][2], z[nt][3],
                        ah[kt][0], ah[kt][1], ah[kt][2], ah[kt][3],
                        Bh[kt][nt][0], Bh[kt][nt][1]);
                mma_f16(z[nt][0], z[nt][1], z[nt][2], z[nt][3],
                        ah[kt][0], ah[kt][1], ah[kt][2], ah[kt][3],
                        bl.x, bl.y);
                mma_f16(z[nt][0], z[nt][1], z[nt][2], z[nt][3],
                        al[kt][0], al[kt][1], al[kt][2], al[kt][3],
                        Bh[kt][nt][0], Bh[kt][nt][1]);
            }
        }
    }

    // ---- RK4 main loop, incremental form ----
    const float DT   = 1.0f / 32.0f;
    const float DT6  = DT / 6.0f;
    const float CMID[3] = {DT * 0.5f, DT * 0.5f, DT};   // A-scale feeding evals e2,e3,e4
    const float SW[3]   = {2.0f, 2.0f, 1.0f};           // s-weight of k2,k3,k4

    float s[8][4];
    uint32_t a[4][4], an[4][4];

    for (int step = 0; step < NSTEPS; ++step) {
        // e1: k1 = tanh(z); s = k1; a = pack(dt/2 * k1)
        #pragma unroll
        for (int nt = 0; nt < 8; ++nt) {
            float k0 = tanh_fast(z[nt][0]);
            float k1 = tanh_fast(z[nt][1]);
            float k2 = tanh_fast(z[nt][2]);
            float k3 = tanh_fast(z[nt][3]);
            s[nt][0] = k0; s[nt][1] = k1; s[nt][2] = k2; s[nt][3] = k3;
            const int kt2 = nt >> 1, sl = (nt & 1) * 2;
            a[kt2][sl]     = pack_h2(CMID[0] * k0, CMID[0] * k1);
            a[kt2][sl + 1] = pack_h2(CMID[0] * k2, CMID[0] * k3);
        }
        // e2..e4: z_e = z + a@Whi ; k = tanh(z_e); s += w*k ; a_next = pack(c*k)
        #pragma unroll
        for (int e = 0; e < 3; ++e) {
            const float sw = SW[e];
            const float cm = (e < 2) ? CMID[e + 1] : 0.0f;  // e4 produces no next A
            #pragma unroll
            for (int nt = 0; nt < 8; ++nt) {
                float c0 = z[nt][0], c1 = z[nt][1], c2 = z[nt][2], c3 = z[nt][3];
                #pragma unroll
                for (int kt = 0; kt < 4; ++kt)
                    mma_f16(c0, c1, c2, c3,
                            a[kt][0], a[kt][1], a[kt][2], a[kt][3],
                            Bh[kt][nt][0], Bh[kt][nt][1]);
                c0 = tanh_fast(c0); c1 = tanh_fast(c1);
                c2 = tanh_fast(c2); c3 = tanh_fast(c3);
                s[nt][0] = fmaf(sw, c0, s[nt][0]);
                s[nt][1] = fmaf(sw, c1, s[nt][1]);
                s[nt][2] = fmaf(sw, c2, s[nt][2]);
                s[nt][3] = fmaf(sw, c3, s[nt][3]);
                if (e < 2) {
                    const int kt2 = nt >> 1, sl = (nt & 1) * 2;
                    an[kt2][sl]     = pack_h2(cm * c0, cm * c1);
                    an[kt2][sl + 1] = pack_h2(cm * c2, cm * c3);
                }
            }
            if (e < 2) {
                #pragma unroll
                for (int kt = 0; kt < 4; ++kt) {
                    a[kt][0] = an[kt][0]; a[kt][1] = an[kt][1];
                    a[kt][2] = an[kt][2]; a[kt][3] = an[kt][3];
                }
            }
        }
        // step: u = dt/6*s; y += u; z += u@Whi  (fp16 residual drift ~1.6e-4, no lo)
        #pragma unroll
        for (int nt = 0; nt < 8; ++nt) {
            float u0 = DT6 * s[nt][0], u1 = DT6 * s[nt][1];
            float u2 = DT6 * s[nt][2], u3 = DT6 * s[nt][3];
            y[nt][0] += u0; y[nt][1] += u1; y[nt][2] += u2; y[nt][3] += u3;
            const int kt2 = nt >> 1, sl = (nt & 1) * 2;
            a[kt2][sl]     = pack_h2(u0, u1);
            a[kt2][sl + 1] = pack_h2(u2, u3);
        }
        #pragma unroll
        for (int nt = 0; nt < 8; ++nt) {
            #pragma unroll
            for (int kt = 0; kt < 4; ++kt)
                mma_f16(z[nt][0], z[nt][1], z[nt][2], z[nt][3],
                        a[kt][0], a[kt][1], a[kt][2], a[kt][3],
                        Bh[kt][nt][0], Bh[kt][nt][1]);
        }
    }

    // ---- readout: out = y1 @ W_out + b_out (fp32) ----
    #pragma unroll
    for (int nt = 0; nt < 8; ++nt) {
        const int c0i = nt * 8 + lam * 2;
        sY[r0][c0i]     = y[nt][0];  sY[r0][c0i + 1]     = y[nt][1];
        sY[r0 + 8][c0i] = y[nt][2];  sY[r0 + 8][c0i + 1] = y[nt][3];
    }
    __syncthreads();
    {
        const int orow = tid >> 1;
        const int ocol = (tid & 1) * 8;
        float o[8];
        #pragma unroll
        for (int j = 0; j < 8; ++j) o[j] = sbout[ocol + j];
        #pragma unroll 4
        for (int k = 0; k < 64; ++k) {
            float yv = sY[orow][k];
            #pragma unroll
            for (int j = 0; j < 8; ++j)
                o[j] = fmaf(yv, sWout[k * 16 + ocol + j], o[j]);
        }
        float4* og = reinterpret_cast<float4*>(out + (rowbase + orow) * 16 + ocol);
        og[0] = make_float4(o[0], o[1], o[2], o[3]);
        og[1] = make_float4(o[4], o[5], o[6], o[7]);
    }
}

}  // namespace ode

extern "C" void kernel_launch(void* const* d_in, const int* in_sizes, int n_in,
                              void* d_out, int out_size) {
    const float* x     = (const float*)d_in[0];
    const float* W_in  = (const float*)d_in[1];
    const float* b_in  = (const float*)d_in[2];
    const float* Wf    = (const float*)d_in[3];
    const float* bfv   = (const float*)d_in[4];
    const float* W_out = (const float*)d_in[5];
    const float* b_out = (const float*)d_in[6];
    float* out = (float*)d_out;

    const int batch = in_sizes[0] / 16;
    const int grid  = batch / 64;
    ode::ode_rk4<<<grid, 128>>>(x, W_in, b_in, Wf, bfv, W_out, b_out, out);
}

// round 6
// speedup vs baseline: 3.4775x; 1.0580x over previous
#include <cuda_runtime.h>
#include <cuda_fp16.h>
#include <stdint.h>

namespace ode {

constexpr int NSTEPS = 32;

__device__ __forceinline__ uint32_t pack_h2(float lo, float hi) {
    __half2 h = __floats2half2_rn(lo, hi);
    return *reinterpret_cast<uint32_t*>(&h);
}
__device__ __forceinline__ uint32_t pack_h2h(__half lo, __half hi) {
    __half2 h = __halves2half2(lo, hi);
    return *reinterpret_cast<uint32_t*>(&h);
}
__device__ __forceinline__ float h_lo(uint32_t p) {
    __half2 h = *reinterpret_cast<__half2*>(&p);
    return __half2float(__low2half(h));
}
__device__ __forceinline__ float h_hi(uint32_t p) {
    __half2 h = *reinterpret_cast<__half2*>(&p);
    return __half2float(__high2half(h));
}
__device__ __forceinline__ uint32_t tanh_h2(uint32_t x) {
    uint32_t r;
    asm("tanh.approx.f16x2 %0, %1;" : "=r"(r) : "r"(x));
    return r;
}
__device__ __forceinline__ uint32_t mul_h2(uint32_t a, uint32_t b) {
    __half2 r = __hmul2(*reinterpret_cast<__half2*>(&a), *reinterpret_cast<__half2*>(&b));
    return *reinterpret_cast<uint32_t*>(&r);
}
__device__ __forceinline__ uint32_t fma_h2(uint32_t a, uint32_t b, uint32_t c) {
    __half2 r = __hfma2(*reinterpret_cast<__half2*>(&a), *reinterpret_cast<__half2*>(&b),
                        *reinterpret_cast<__half2*>(&c));
    return *reinterpret_cast<uint32_t*>(&r);
}

__device__ __forceinline__ void mma_f16(float& c0, float& c1, float& c2, float& c3,
                                        uint32_t a0, uint32_t a1, uint32_t a2, uint32_t a3,
                                        uint32_t b0, uint32_t b1) {
    asm volatile(
        "mma.sync.aligned.m16n8k16.row.col.f32.f16.f16.f32 "
        "{%0,%1,%2,%3}, {%4,%5,%6,%7}, {%8,%9}, {%0,%1,%2,%3};"
        : "+f"(c0), "+f"(c1), "+f"(c2), "+f"(c3)
        : "r"(a0), "r"(a1), "r"(a2), "r"(a3), "r"(b0), "r"(b1));
}

// RK4 in incremental (delta-z) form, fp16 weights, fp16x2 tanh + packed combine:
//   z = y@Wf + bf carried in fp32; per step (per warp): 128 HMMA, 64 f16x2 MUFU.
//   u = dt/6 k1 + dt/3 k2 + dt/3 k3 + dt/6 k4 accumulated in f16x2 packed regs;
//   the step-update A fragment IS u_p (no packing). y updated in fp32.
__global__ void __launch_bounds__(128, 2)
ode_rk4(const float* __restrict__ x,
        const float* __restrict__ W_in,
        const float* __restrict__ b_in,
        const float* __restrict__ Wf,
        const float* __restrict__ bfv,
        const float* __restrict__ W_out,
        const float* __restrict__ b_out,
        float* __restrict__ out) {
    __shared__ float sX[64][17];
    __shared__ float sWin[16 * 64];
    __shared__ float sWout[64 * 16];
    __shared__ float sbin[64];
    __shared__ float sbf[64];
    __shared__ float sbout[16];
    __shared__ float sY[64][65];
    __shared__ uint2 sBl[4][8][32];   // Wlo fp16 residual fragments (base z0 only)

    const int tid  = threadIdx.x;
    const int lane = tid & 31;
    const int warp = tid >> 5;
    const int g    = lane >> 2;
    const int lam  = lane & 3;
    const long rowbase = (long)blockIdx.x * 64;

    // ---- stage x tile ----
    {
        const float4* xg = reinterpret_cast<const float4*>(x + rowbase * 16);
        #pragma unroll
        for (int i = 0; i < 2; ++i) {
            int idx = tid + i * 128;
            float4 v = xg[idx];
            int r = idx >> 2, c = (idx & 3) << 2;
            sX[r][c] = v.x; sX[r][c + 1] = v.y; sX[r][c + 2] = v.z; sX[r][c + 3] = v.w;
        }
    }
    for (int i = tid; i < 16 * 64; i += 128) sWin[i]  = W_in[i];
    for (int i = tid; i < 64 * 16; i += 128) sWout[i] = W_out[i];
    if (tid < 64) { sbin[tid] = b_in[tid]; sbf[tid] = bfv[tid]; }
    if (tid < 16) sbout[tid] = b_out[tid];

    // ---- Whi (fp16) fragments in registers; Wlo residuals to SMEM ----
    uint32_t Bh[4][8][2];
    #pragma unroll
    for (int kt = 0; kt < 4; ++kt) {
        #pragma unroll
        for (int nt = 0; nt < 8; ++nt) {
            const float* wp = Wf + (kt * 16 + lam * 2) * 64 + nt * 8 + g;
            float w00 = __ldg(wp);
            float w01 = __ldg(wp + 64);
            float w10 = __ldg(wp + 8 * 64);
            float w11 = __ldg(wp + 9 * 64);
            __half h00 = __float2half_rn(w00);
            __half h01 = __float2half_rn(w01);
            __half h10 = __float2half_rn(w10);
            __half h11 = __float2half_rn(w11);
            Bh[kt][nt][0] = pack_h2h(h00, h01);
            Bh[kt][nt][1] = pack_h2h(h10, h11);
            uint2 lo;
            lo.x = pack_h2(w00 - __half2float(h00), w01 - __half2float(h01));
            lo.y = pack_h2(w10 - __half2float(h10), w11 - __half2float(h11));
            sBl[kt][nt][lane] = lo;
        }
    }
    __syncthreads();

    // ---- y0 = x @ W_in + b_in (fp32, fragment layout) ----
    const int r0 = warp * 16 + g;
    float y[8][4];
    #pragma unroll
    for (int nt = 0; nt < 8; ++nt) {
        const int c0i = nt * 8 + lam * 2;
        y[nt][0] = sbin[c0i];  y[nt][1] = sbin[c0i + 1];
        y[nt][2] = sbin[c0i];  y[nt][3] = sbin[c0i + 1];
    }
    #pragma unroll 4
    for (int i = 0; i < 16; ++i) {
        float xa = sX[r0][i];
        float xb = sX[r0 + 8][i];
        #pragma unroll
        for (int nt = 0; nt < 8; ++nt) {
            float w0 = sWin[i * 64 + nt * 8 + lam * 2];
            float w1 = sWin[i * 64 + nt * 8 + lam * 2 + 1];
            y[nt][0] = fmaf(xa, w0, y[nt][0]);
            y[nt][1] = fmaf(xa, w1, y[nt][1]);
            y[nt][2] = fmaf(xb, w0, y[nt][2]);
            y[nt][3] = fmaf(xb, w1, y[nt][3]);
        }
    }

    // ---- base z0 = y0 @ Wf + bf, high precision: y0h@(Whi+Wlo) + y0l@Whi ----
    float z[8][4];
    {
        uint32_t ah[4][4], al[4][4];
        #pragma unroll
        for (int kt = 0; kt < 4; ++kt) {
            const int nA = 2 * kt, nB = 2 * kt + 1;
            ah[kt][0] = pack_h2(y[nA][0], y[nA][1]);
            ah[kt][1] = pack_h2(y[nA][2], y[nA][3]);
            ah[kt][2] = pack_h2(y[nB][0], y[nB][1]);
            ah[kt][3] = pack_h2(y[nB][2], y[nB][3]);
            al[kt][0] = pack_h2(y[nA][0] - h_lo(ah[kt][0]), y[nA][1] - h_hi(ah[kt][0]));
            al[kt][1] = pack_h2(y[nA][2] - h_lo(ah[kt][1]), y[nA][3] - h_hi(ah[kt][1]));
            al[kt][2] = pack_h2(y[nB][0] - h_lo(ah[kt][2]), y[nB][1] - h_hi(ah[kt][2]));
            al[kt][3] = pack_h2(y[nB][2] - h_lo(ah[kt][3]), y[nB][3] - h_hi(ah[kt][3]));
        }
        #pragma unroll
        for (int nt = 0; nt < 8; ++nt) {
            const float2 bb = *reinterpret_cast<const float2*>(&sbf[nt * 8 + lam * 2]);
            z[nt][0] = bb.x; z[nt][1] = bb.y; z[nt][2] = bb.x; z[nt][3] = bb.y;
            #pragma unroll
            for (int kt = 0; kt < 4; ++kt) {
                uint2 bl = sBl[kt][nt][lane];
                mma_f16(z[nt][0], z[nt][1], z[nt][2], z[nt][3],
                        ah[kt][0], ah[kt][1], ah[kt][2], ah[kt][3],
                        Bh[kt][nt][0], Bh[kt][nt][1]);
                mma_f16(z[nt][0], z[nt][1], z[nt][2], z[nt][3],
                        ah[kt][0], ah[kt][1], ah[kt][2], ah[kt][3],
                        bl.x, bl.y);
                mma_f16(z[nt][0], z[nt][1], z[nt][2], z[nt][3],
                        al[kt][0], al[kt][1], al[kt][2], al[kt][3],
                        Bh[kt][nt][0], Bh[kt][nt][1]);
            }
        }
    }

    // ---- RK4 main loop: packed-fp16 tanh + combine ----
    const uint32_t DT6p = pack_h2(1.0f / 192.0f, 1.0f / 192.0f);  // dt/6
    const uint32_t DT3p = pack_h2(1.0f / 96.0f,  1.0f / 96.0f);   // dt/3
    const uint32_t DTHp = pack_h2(1.0f / 64.0f,  1.0f / 64.0f);   // dt/2
    const uint32_t DTp  = pack_h2(1.0f / 32.0f,  1.0f / 32.0f);   // dt

    uint32_t up[8][2];          // packed u accumulator
    uint32_t a[4][4], an[4][4];

    for (int step = 0; step < NSTEPS; ++step) {
        // e1: k1 = tanh(z); u = dt/6*k1; a = dt/2*k1
        #pragma unroll
        for (int nt = 0; nt < 8; ++nt) {
            uint32_t k0 = tanh_h2(pack_h2(z[nt][0], z[nt][1]));
            uint32_t k1 = tanh_h2(pack_h2(z[nt][2], z[nt][3]));
            up[nt][0] = mul_h2(k0, DT6p);
            up[nt][1] = mul_h2(k1, DT6p);
            const int kt2 = nt >> 1, sl = (nt & 1) * 2;
            a[kt2][sl]     = mul_h2(k0, DTHp);
            a[kt2][sl + 1] = mul_h2(k1, DTHp);
        }
        // e2, e3: z_e = z + a@Whi; k = tanh; u += dt/3*k; a_next = cm*k
        #pragma unroll
        for (int e = 0; e < 2; ++e) {
            const uint32_t cmp = (e == 0) ? DTHp : DTp;
            #pragma unroll
            for (int nt = 0; nt < 8; ++nt) {
                float c0 = z[nt][0], c1 = z[nt][1], c2 = z[nt][2], c3 = z[nt][3];
                #pragma unroll
                for (int kt = 0; kt < 4; ++kt)
                    mma_f16(c0, c1, c2, c3,
                            a[kt][0], a[kt][1], a[kt][2], a[kt][3],
                            Bh[kt][nt][0], Bh[kt][nt][1]);
                uint32_t k0 = tanh_h2(pack_h2(c0, c1));
                uint32_t k1 = tanh_h2(pack_h2(c2, c3));
                up[nt][0] = fma_h2(k0, DT3p, up[nt][0]);
                up[nt][1] = fma_h2(k1, DT3p, up[nt][1]);
                const int kt2 = nt >> 1, sl = (nt & 1) * 2;
                an[kt2][sl]     = mul_h2(k0, cmp);
                an[kt2][sl + 1] = mul_h2(k1, cmp);
            }
            #pragma unroll
            for (int kt = 0; kt < 4; ++kt) {
                a[kt][0] = an[kt][0]; a[kt][1] = an[kt][1];
                a[kt][2] = an[kt][2]; a[kt][3] = an[kt][3];
            }
        }
        // e4: z4 = z + a@Whi; k4 = tanh; u += dt/6*k4; a(step) = u_p directly
        #pragma unroll
        for (int nt = 0; nt < 8; ++nt) {
            float c0 = z[nt][0], c1 = z[nt][1], c2 = z[nt][2], c3 = z[nt][3];
            #pragma unroll
            for (int kt = 0; kt < 4; ++kt)
                mma_f16(c0, c1, c2, c3,
                        a[kt][0], a[kt][1], a[kt][2], a[kt][3],
                        Bh[kt][nt][0], Bh[kt][nt][1]);
            uint32_t k0 = tanh_h2(pack_h2(c0, c1));
            uint32_t k1 = tanh_h2(pack_h2(c2, c3));
            up[nt][0] = fma_h2(k0, DT6p, up[nt][0]);
            up[nt][1] = fma_h2(k1, DT6p, up[nt][1]);
            const int kt2 = nt >> 1, sl = (nt & 1) * 2;
            an[kt2][sl]     = up[nt][0];
            an[kt2][sl + 1] = up[nt][1];
        }
        // step: y += u (fp32); z += u@Whi
        #pragma unroll
        for (int nt = 0; nt < 8; ++nt) {
            y[nt][0] += h_lo(up[nt][0]); y[nt][1] += h_hi(up[nt][0]);
            y[nt][2] += h_lo(up[nt][1]); y[nt][3] += h_hi(up[nt][1]);
        }
        #pragma unroll
        for (int nt = 0; nt < 8; ++nt) {
            #pragma unroll
            for (int kt = 0; kt < 4; ++kt)
                mma_f16(z[nt][0], z[nt][1], z[nt][2], z[nt][3],
                        an[kt][0], an[kt][1], an[kt][2], an[kt][3],
                        Bh[kt][nt][0], Bh[kt][nt][1]);
        }
    }

    // ---- readout: out = y1 @ W_out + b_out (fp32) ----
    #pragma unroll
    for (int nt = 0; nt < 8; ++nt) {
        const int c0i = nt * 8 + lam * 2;
        sY[r0][c0i]     = y[nt][0];  sY[r0][c0i + 1]     = y[nt][1];
        sY[r0 + 8][c0i] = y[nt][2];  sY[r0 + 8][c0i + 1] = y[nt][3];
    }
    __syncthreads();
    {
        const int orow = tid >> 1;
        const int ocol = (tid & 1) * 8;
        float o[8];
        #pragma unroll
        for (int j = 0; j < 8; ++j) o[j] = sbout[ocol + j];
        #pragma unroll 4
        for (int k = 0; k < 64; ++k) {
            float yv = sY[orow][k];
            #pragma unroll
            for (int j = 0; j < 8; ++j)
                o[j] = fmaf(yv, sWout[k * 16 + ocol + j], o[j]);
        }
        float4* og = reinterpret_cast<float4*>(out + (rowbase + orow) * 16 + ocol);
        og[0] = make_float4(o[0], o[1], o[2], o[3]);
        og[1] = make_float4(o[4], o[5], o[6], o[7]);
    }
}

}  // namespace ode

extern "C" void kernel_launch(void* const* d_in, const int* in_sizes, int n_in,
                              void* d_out, int out_size) {
    const float* x     = (const float*)d_in[0];
    const float* W_in  = (const float*)d_in[1];
    const float* b_in  = (const float*)d_in[2];
    const float* Wf    = (const float*)d_in[3];
    const float* bfv   = (const float*)d_in[4];
    const float* W_out = (const float*)d_in[5];
    const float* b_out = (const float*)d_in[6];
    float* out = (float*)d_out;

    const int batch = in_sizes[0] / 16;
    const int grid  = batch / 64;
    ode::ode_rk4<<<grid, 128>>>(x, W_in, b_in, Wf, bfv, W_out, b_out, out);
}